// round 14
// baseline (speedup 1.0000x reference)
#include <cuda_runtime.h>
#include <cuda_bf16.h>
#include <cuda_fp16.h>
#include <mma.h>
#include <cstdint>

using namespace nvcuda;

#define NN 50000
#define NE 800000
#define D 128
#define NB 148
#define NT 512
#define GS (NB * NT)
#define NWARPS (NT / 32)             // 16
#define CHUNK ((NN + NB - 1) / NB)   // 338
#define NT64 ((NN + 63) / 64)        // 782 64-row tiles
#define LDA 136                       // bf16 smem leading dim (272 B rows)
#define LDS_ 132                      // f32 staging leading dim
#define WSZ (128 * 136)               // one split-W plane (elements)

// smem byte offsets (within 1024-aligned base)
#define O_WLH 0
#define O_WLL 34816
#define O_WRH 69632
#define O_WRL 104448
#define O_AX  139264                  // a1 buffer (hi 17408 + lo 17408)
#define O_AY  174080                  // mean buffer / staging
#define SMEM_BYTES (208896 + 1024)

typedef unsigned long long u64;

// -------- device scratch --------
__device__ unsigned g_gen = 0;
__device__ unsigned g_arrive = 0;
__device__ int   g_cnt[NN];
__device__ int   g_off[NN + 1];
__device__ int   g_pos[NN];
__device__ int   g_srcs[NE];
__device__ int   g_bsum[NB];
__device__ float g_ps[NB * D];
__device__ float g_ps2[NB * D];
// pre-split weights (6 matrices, ld=136; padding zero-init)
__device__ __nv_bfloat16 g_wh[6 * WSZ];
__device__ __nv_bfloat16 g_wl[6 * WSZ];
// split-bf16 + fp16 feature buffers (ld = 128)
__device__ __nv_bfloat16 g_xh[NN * D];
__device__ __nv_bfloat16 g_xl[NN * D];
__device__ __half        g_x16[NN * D];
__device__ __nv_bfloat16 g_mh[NN * D];
__device__ __nv_bfloat16 g_ml[NN * D];
__device__ __nv_bfloat16 g_h0h[NN * D];
__device__ __nv_bfloat16 g_h0l[NN * D];
__device__ __half        g_h016[NN * D];
__device__ __nv_bfloat16 g_h1h[NN * D];
__device__ __nv_bfloat16 g_h1l[NN * D];
__device__ __half        g_h116[NN * D];

// -------- helpers --------
__device__ __forceinline__ uint32_t cvt2(float lo, float hi) {
    uint32_t r;
    asm("cvt.rn.bf16x2.f32 %0, %1, %2;" : "=r"(r) : "f"(hi), "f"(lo));
    return r;
}
__device__ __forceinline__ void split4(float4 v, uint2& h, uint2& l) {
    uint32_t h0 = cvt2(v.x, v.y);
    uint32_t h1 = cvt2(v.z, v.w);
    uint32_t l0 = cvt2(v.x - __uint_as_float(h0 << 16),
                       v.y - __uint_as_float(h0 & 0xffff0000u));
    uint32_t l1 = cvt2(v.z - __uint_as_float(h1 << 16),
                       v.w - __uint_as_float(h1 & 0xffff0000u));
    h = make_uint2(h0, h1);
    l = make_uint2(l0, l1);
}
__device__ __forceinline__ uint2 half4(float4 v) {
    uint2 r;
    *(__half2*)&r.x = __floats2half2_rn(v.x, v.y);
    *(__half2*)&r.y = __floats2half2_rn(v.z, v.w);
    return r;
}
__device__ __forceinline__ float4 rec4(uint2 h, uint2 l) {
    float4 v;
    v.x = __uint_as_float(h.x << 16) + __uint_as_float(l.x << 16);
    v.y = __uint_as_float(h.x & 0xffff0000u) + __uint_as_float(l.x & 0xffff0000u);
    v.z = __uint_as_float(h.y << 16) + __uint_as_float(l.y << 16);
    v.w = __uint_as_float(h.y & 0xffff0000u) + __uint_as_float(l.y & 0xffff0000u);
    return v;
}
__device__ __forceinline__ void cpa16(uint32_t saddr, const void* gptr) {
    asm volatile("cp.async.cg.shared.global [%0], [%1], 16;"
                 :: "r"(saddr), "l"(gptr) : "memory");
}
#define CP_COMMIT() asm volatile("cp.async.commit_group;" ::: "memory")
#define CP_WAIT0()  asm volatile("cp.async.wait_group 0;" ::: "memory")

// -------- grid-wide software barrier --------
__device__ __forceinline__ void gbar() {
    __syncthreads();
    if (threadIdx.x == 0) {
        __threadfence();
        unsigned gen = atomicAdd(&g_gen, 0u);
        unsigned arrived = atomicAdd(&g_arrive, 1u) + 1u;
        if (arrived == NB) {
            atomicExch(&g_arrive, 0u);
            __threadfence();
            atomicAdd(&g_gen, 1u);
        } else {
            while (atomicAdd(&g_gen, 0u) == gen) { __nanosleep(128); }
        }
        __threadfence();
    }
    __syncthreads();
}

// -------- mean aggregation: fp16 gather, split-bf16 mean output --------
__device__ __forceinline__ void agg_phase(const __half* __restrict__ h16) {
    const int lane = threadIdx.x & 31;
    const int warp = threadIdx.x >> 5;
    const int gw0 = blockIdx.x * NWARPS + warp;
    for (int n = gw0; n < NN; n += NB * NWARPS) {
        int beg = g_off[n];
        int end = g_off[n + 1];
        float4 a0 = make_float4(0.f, 0.f, 0.f, 0.f);
        float4 a1 = make_float4(0.f, 0.f, 0.f, 0.f);
        int i = beg;
#define GATHER1(s, acc) do { \
            uint2 u = __ldg((const uint2*)(h16 + (size_t)(s) * D + lane * 4)); \
            float2 p = __half22float2(*(const __half2*)&u.x); \
            float2 q = __half22float2(*(const __half2*)&u.y); \
            (acc).x += p.x; (acc).y += p.y; (acc).z += q.x; (acc).w += q.y; } while (0)
        for (; i + 7 < end; i += 8) {
            int s0 = __ldg(&g_srcs[i]);
            int s1 = __ldg(&g_srcs[i + 1]);
            int s2 = __ldg(&g_srcs[i + 2]);
            int s3 = __ldg(&g_srcs[i + 3]);
            int s4 = __ldg(&g_srcs[i + 4]);
            int s5 = __ldg(&g_srcs[i + 5]);
            int s6 = __ldg(&g_srcs[i + 6]);
            int s7 = __ldg(&g_srcs[i + 7]);
            GATHER1(s0, a0); GATHER1(s1, a0); GATHER1(s2, a0); GATHER1(s3, a0);
            GATHER1(s4, a1); GATHER1(s5, a1); GATHER1(s6, a1); GATHER1(s7, a1);
        }
        for (; i < end; i++) { GATHER1(__ldg(&g_srcs[i]), a0); }
#undef GATHER1
        float inv = 1.0f / fmaxf((float)(end - beg), 1.0f);
        float4 r;
        r.x = (a0.x + a1.x) * inv;
        r.y = (a0.y + a1.y) * inv;
        r.z = (a0.z + a1.z) * inv;
        r.w = (a0.w + a1.w) * inv;
        uint2 hh, ll;
        split4(r, hh, ll);
        *(uint2*)(g_mh + (size_t)n * D + lane * 4) = hh;
        *(uint2*)(g_ml + (size_t)n * D + lane * 4) = ll;
    }
}

// -------- 64-row A-tile async copy: 2048 x 16B --------
__device__ __forceinline__ void copy64_async(const __nv_bfloat16* __restrict__ Ah,
                                             const __nv_bfloat16* __restrict__ Al,
                                             int row0, uint32_t sdst) {
#pragma unroll
    for (int it = 0; it < 4; it++) {
        int idx = threadIdx.x + it * NT;   // 0..2047
        int plane = idx >> 10;
        int rem = idx & 1023;
        int r = rem >> 4, g = rem & 15;
        int row = min(row0 + r, NN - 1);
        const __nv_bfloat16* src = (plane ? Al : Ah) + (size_t)row * D + g * 8;
        cpa16(sdst + plane * 17408 + r * 272 + g * 16, src);
    }
}

// -------- MMA over one operand pair, 64-row tile, 16 warps (4x4 grid) ----
__device__ __forceinline__ void mma64(
    wmma::fragment<wmma::accumulator, 16, 16, 16, float> fc[2],
    const __nv_bfloat16* ahi, const __nv_bfloat16* alo,
    const __nv_bfloat16* wh, const __nv_bfloat16* wl,
    int wr_, int wc_) {
#pragma unroll
    for (int ks = 0; ks < 8; ks++) {
        wmma::fragment<wmma::matrix_a, 16, 16, 16, __nv_bfloat16,
                       wmma::row_major> fa_hi, fa_lo;
        wmma::fragment<wmma::matrix_b, 16, 16, 16, __nv_bfloat16,
                       wmma::col_major> fb_hi[2], fb_lo[2];
        const int r = wr_ * 16;
        wmma::load_matrix_sync(fa_hi, ahi + r * LDA + ks * 16, LDA);
        wmma::load_matrix_sync(fa_lo, alo + r * LDA + ks * 16, LDA);
#pragma unroll
        for (int j = 0; j < 2; j++) {
            const int c = wc_ * 32 + j * 16;
            wmma::load_matrix_sync(fb_hi[j], wh + c * LDA + ks * 16, LDA);
            wmma::load_matrix_sync(fb_lo[j], wl + c * LDA + ks * 16, LDA);
        }
#pragma unroll
        for (int j = 0; j < 2; j++) {
            wmma::mma_sync(fc[j], fa_hi, fb_hi[j], fc[j]);
            wmma::mma_sync(fc[j], fa_hi, fb_lo[j], fc[j]);
            wmma::mma_sync(fc[j], fa_lo, fb_hi[j], fc[j]);
        }
    }
}

// -------- cp.async pipelined fused dual GEMM: out = mean@Wl + a1@Wr + b ----
// MODE 0: relu -> (oh,ol,o16). MODE 1: -> (oh,ol) + BN partials. MODE 2: fp32.
template <int MODE>
__device__ __forceinline__ void gemm_cp(
    const __nv_bfloat16* __restrict__ a1h, const __nv_bfloat16* __restrict__ a1l,
    int wml, int wmr,
    const float* __restrict__ bias,
    float* __restrict__ outf,
    __nv_bfloat16* __restrict__ oh, __nv_bfloat16* __restrict__ ol,
    __half* __restrict__ o16, char* base) {
    __nv_bfloat16* wlh = (__nv_bfloat16*)(base + O_WLH);
    __nv_bfloat16* wll = (__nv_bfloat16*)(base + O_WLL);
    __nv_bfloat16* wrh = (__nv_bfloat16*)(base + O_WRH);
    __nv_bfloat16* wrl = (__nv_bfloat16*)(base + O_WRL);
    __nv_bfloat16* Xhi = (__nv_bfloat16*)(base + O_AX);
    __nv_bfloat16* Xlo = (__nv_bfloat16*)(base + O_AX + 17408);
    __nv_bfloat16* Yhi = (__nv_bfloat16*)(base + O_AY);
    __nv_bfloat16* Ylo = (__nv_bfloat16*)(base + O_AY + 17408);
    float* staging = (float*)(base + O_AY);

    const uint32_t sbase = (uint32_t)__cvta_generic_to_shared(base);
    const uint32_t sX = sbase + O_AX;
    const uint32_t sY = sbase + O_AY;

    const int tid = threadIdx.x;
    const int warp = tid >> 5;
    const int wr_ = warp >> 2;   // 0..3 -> rows wr_*16
    const int wc_ = warp & 3;    // 0..3 -> cols wc_*32

    // prologue: async W fill + first a1 tile
    {
        const char* s0 = (const char*)(g_wh + wml * WSZ);
        const char* s1 = (const char*)(g_wl + wml * WSZ);
        const char* s2 = (const char*)(g_wh + wmr * WSZ);
        const char* s3 = (const char*)(g_wl + wmr * WSZ);
        for (int i = tid; i < 2176; i += NT) {
            cpa16(sbase + O_WLH + i * 16, s0 + i * 16);
            cpa16(sbase + O_WLL + i * 16, s1 + i * 16);
            cpa16(sbase + O_WRH + i * 16, s2 + i * 16);
            cpa16(sbase + O_WRL + i * 16, s3 + i * 16);
        }
    }
    copy64_async(a1h, a1l, blockIdx.x * 64, sX);
    CP_COMMIT();
    CP_WAIT0();
    __syncthreads();

    float bn_s[4] = {0.f, 0.f, 0.f, 0.f};
    float bn_s2[4] = {0.f, 0.f, 0.f, 0.f};

    for (int t = blockIdx.x; t < NT64; t += NB) {
        const int row0 = t * 64;
        wmma::fragment<wmma::accumulator, 16, 16, 16, float> fc[2];
#pragma unroll
        for (int j = 0; j < 2; j++) wmma::fill_fragment(fc[j], 0.f);

        // issue mean(t) copy; overlap with a1 MMA
        copy64_async(g_mh, g_ml, row0, sY);
        CP_COMMIT();
        mma64(fc, Xhi, Xlo, wrh, wrl, wr_, wc_);   // a1 @ Wr
        CP_WAIT0();
        __syncthreads();

        // issue a1(t+NB) copy; overlap with mean MMA + staging + epilogue
        int tn = t + NB;
        if (tn < NT64) copy64_async(a1h, a1l, tn * 64, sX);
        CP_COMMIT();
        mma64(fc, Yhi, Ylo, wlh, wll, wr_, wc_);   // mean @ Wl
        __syncthreads();

        // stage accumulators into Y region
#pragma unroll
        for (int j = 0; j < 2; j++)
            wmma::store_matrix_sync(
                staging + (wr_ * 16) * LDS_ + wc_ * 32 + j * 16,
                fc[j], LDS_, wmma::mem_row_major);
        __syncthreads();

        // epilogue: 64 rows x 32 col-quads
        const int cq = tid & 31;
        float4 b4 = *(const float4*)(bias + cq * 4);
#pragma unroll
        for (int it = 0; it < 4; it++) {
            int idx = tid + it * NT;
            int r = idx >> 5;
            int row = row0 + r;
            if (row < NN) {
                float4 v = *(const float4*)(staging + r * LDS_ + cq * 4);
                v.x += b4.x; v.y += b4.y; v.z += b4.z; v.w += b4.w;
                size_t off = (size_t)row * D + cq * 4;
                if (MODE == 0) {
                    v.x = fmaxf(v.x, 0.f); v.y = fmaxf(v.y, 0.f);
                    v.z = fmaxf(v.z, 0.f); v.w = fmaxf(v.w, 0.f);
                    uint2 hh, ll;
                    split4(v, hh, ll);
                    *(uint2*)(oh + off) = hh;
                    *(uint2*)(ol + off) = ll;
                    *(uint2*)(o16 + off) = half4(v);
                } else if (MODE == 1) {
                    bn_s[0] += v.x; bn_s[1] += v.y;
                    bn_s[2] += v.z; bn_s[3] += v.w;
                    bn_s2[0] += v.x * v.x; bn_s2[1] += v.y * v.y;
                    bn_s2[2] += v.z * v.z; bn_s2[3] += v.w * v.w;
                    uint2 hh, ll;
                    split4(v, hh, ll);
                    *(uint2*)(oh + off) = hh;
                    *(uint2*)(ol + off) = ll;
                } else {
                    *(float4*)(outf + off) = v;
                }
            }
        }
        CP_WAIT0();        // a1(t+NB) landed
        __syncthreads();   // epilogue reads done before next mean copy into Y
    }

    if (MODE == 1) {
        float* bs = (float*)(base + O_AY);
#pragma unroll
        for (int j = 0; j < 4; j++) {
            bs[j * NT + tid] = bn_s[j];
            bs[4 * NT + j * NT + tid] = bn_s2[j];
        }
        __syncthreads();
        if (tid < D) {
            int l = tid >> 2, j = tid & 3;
            float s = 0.f, s2 = 0.f;
#pragma unroll
            for (int w = 0; w < 16; w++) {
                s += bs[j * NT + l + w * 32];
                s2 += bs[4 * NT + j * NT + l + w * 32];
            }
            g_ps[blockIdx.x * D + tid] = s;
            g_ps2[blockIdx.x * D + tid] = s2;
        }
        __syncthreads();
    }
}

// -------- the mono-kernel --------
__global__ void __launch_bounds__(NT, 1)
mono_kernel(const float* __restrict__ x,
            const int* __restrict__ src, const int* __restrict__ dst,
            const float* __restrict__ Wl0, const float* __restrict__ bl0,
            const float* __restrict__ Wr0,
            const float* __restrict__ Wl1, const float* __restrict__ bl1,
            const float* __restrict__ Wr1,
            const float* __restrict__ Wl2, const float* __restrict__ bl2,
            const float* __restrict__ Wr2,
            const float* __restrict__ gamma, const float* __restrict__ beta,
            float* __restrict__ out) {
    extern __shared__ char smc[];
    char* base = (char*)(((uintptr_t)smc + 1023) & ~(uintptr_t)1023);
    const int tid = threadIdx.x;
    const int bid = blockIdx.x;
    const int gt = bid * NT + tid;
    const int lane = tid & 31;
    const int warp = tid >> 5;

    // ---- phase 1: histogram + split x + split all 6 W ----
    for (int e = gt; e < NE; e += GS) atomicAdd(&g_cnt[dst[e]], 1);
    for (int i = gt; i < NN * 32; i += GS) {
        float4 v = __ldg((const float4*)(x + (size_t)i * 4));
        uint2 h, l;
        split4(v, h, l);
        ((uint2*)g_xh)[i] = h;
        ((uint2*)g_xl)[i] = l;
        ((uint2*)g_x16)[i] = half4(v);
    }
    {
        const float* wm[6] = {Wl0, Wr0, Wl1, Wr1, Wl2, Wr2};
        for (int i = gt; i < 6 * 4096; i += GS) {
            int m = i >> 12;
            int rem = i & 4095;
            int r = rem >> 5, kq = rem & 31;
            float4 v = __ldg((const float4*)(wm[m] + r * D + kq * 4));
            uint2 h, l;
            split4(v, h, l);
            *(uint2*)(g_wh + m * WSZ + r * LDA + kq * 4) = h;
            *(uint2*)(g_wl + m * WSZ + r * LDA + kq * 4) = l;
        }
    }
    gbar();

    // ---- phase 2: per-block chunk sums ----
    {
        __shared__ int red[NWARPS];
        int cb = bid * CHUNK;
        int v = 0;
        for (int i = tid; i < CHUNK; i += NT) {
            int idx = cb + i;
            if (idx < NN) v += g_cnt[idx];
        }
#pragma unroll
        for (int o = 16; o > 0; o >>= 1) v += __shfl_down_sync(0xffffffffu, v, o);
        if (lane == 0) red[warp] = v;
        __syncthreads();
        if (warp == 0) {
            int w = (lane < NWARPS) ? red[lane] : 0;
#pragma unroll
            for (int o = 8; o > 0; o >>= 1) w += __shfl_down_sync(0xffffffffu, w, o);
            if (lane == 0) g_bsum[bid] = w;
        }
    }
    gbar();

    // ---- phase 3: every block scans block sums locally ----
    __shared__ int s_boff;
    {
        __shared__ int sb[NB];
        if (tid < NB) sb[tid] = g_bsum[tid];
        __syncthreads();
        if (tid == 0) {
            int run = 0;
            for (int b = 0; b < NB; b++) { int v = sb[b]; sb[b] = run; run += v; }
            s_boff = sb[bid];
        }
        __syncthreads();
        if (bid == NB - 1 && tid == 0) g_off[NN] = NE;
    }

    // ---- phase 4: write offsets, reset g_cnt ----
    {
        __shared__ int wsum[NWARPS];
        int cb = bid * CHUNK;
        int idx = cb + tid;
        int v = (tid < CHUNK && idx < NN) ? g_cnt[idx] : 0;
        int inc = v;
#pragma unroll
        for (int o = 1; o < 32; o <<= 1) {
            int u = __shfl_up_sync(0xffffffffu, inc, o);
            if (lane >= o) inc += u;
        }
        if (lane == 31) wsum[warp] = inc;
        __syncthreads();
        if (warp == 0) {
            int w = (lane < NWARPS) ? wsum[lane] : 0;
            int wi = w;
#pragma unroll
            for (int o = 1; o < NWARPS; o <<= 1) {
                int u = __shfl_up_sync(0xffffffffu, wi, o);
                if (lane >= o) wi += u;
            }
            if (lane < NWARPS) wsum[lane] = wi - w;
        }
        __syncthreads();
        int excl = s_boff + wsum[warp] + inc - v;
        if (tid < CHUNK && idx < NN) {
            g_off[idx] = excl;
            g_pos[idx] = excl;
            g_cnt[idx] = 0;
        }
    }
    gbar();

    // ---- phase 5: scatter src by dst ----
    for (int e = gt; e < NE; e += GS) {
        int p = atomicAdd(&g_pos[dst[e]], 1);
        g_srcs[p] = src[e];
    }
    gbar();

    // ---- layer 0 ----
    agg_phase(g_x16);
    gbar();
    gemm_cp<0>(g_xh, g_xl, 0, 1, bl0, nullptr, g_h0h, g_h0l, g_h016, base);
    gbar();

    // ---- layer 1 ----
    agg_phase(g_h016);
    gbar();
    gemm_cp<1>(g_h0h, g_h0l, 2, 3, bl1, nullptr, g_h1h, g_h1l, nullptr, base);
    gbar();

    // ---- batchnorm finalize (replicated) + apply + relu ----
    {
        __shared__ float s_scale[D], s_shift[D];
        __shared__ float r1[NT], r2[NT];
        int col = tid & 127;
        int part = tid >> 7;  // 0..3
        float s = 0.f, s2 = 0.f;
        for (int b = part; b < NB; b += 4) {
            s += g_ps[b * D + col];
            s2 += g_ps2[b * D + col];
        }
        r1[tid] = s; r2[tid] = s2;
        __syncthreads();
        if (part == 0) {
            double S = (double)r1[col] + (double)r1[col + 128] +
                       (double)r1[col + 256] + (double)r1[col + 384];
            double S2 = (double)r2[col] + (double)r2[col + 128] +
                        (double)r2[col + 256] + (double)r2[col + 384];
            double mu = S / (double)NN;
            double var = S2 / (double)NN - mu * mu;
            float inv = rsqrtf((float)var + 1e-5f);
            float sc = inv * gamma[col];
            s_scale[col] = sc;
            s_shift[col] = beta[col] - (float)mu * sc;
        }
        __syncthreads();
        for (int i = gt; i < NN * 32; i += GS) {
            uint2 hh = ((const uint2*)g_h1h)[i];
            uint2 ll = ((const uint2*)g_h1l)[i];
            float4 v = rec4(hh, ll);
            int c = (i & 31) * 4;
            v.x = fmaxf(fmaf(v.x, s_scale[c + 0], s_shift[c + 0]), 0.f);
            v.y = fmaxf(fmaf(v.y, s_scale[c + 1], s_shift[c + 1]), 0.f);
            v.z = fmaxf(fmaf(v.z, s_scale[c + 2], s_shift[c + 2]), 0.f);
            v.w = fmaxf(fmaf(v.w, s_scale[c + 3], s_shift[c + 3]), 0.f);
            uint2 nh, nl;
            split4(v, nh, nl);
            ((uint2*)g_h1h)[i] = nh;
            ((uint2*)g_h1l)[i] = nl;
            ((uint2*)g_h116)[i] = half4(v);
        }
    }
    gbar();

    // ---- layer 2 ----
    agg_phase(g_h116);
    gbar();
    gemm_cp<2>(g_h1h, g_h1l, 4, 5, bl2, out, nullptr, nullptr, nullptr, base);
}

// -------- launch --------
extern "C" void kernel_launch(void* const* d_in, const int* in_sizes, int n_in,
                              void* d_out, int out_size) {
    const float* x     = (const float*)d_in[0];
    const int*   ei    = (const int*)d_in[1];
    const float* Wl0   = (const float*)d_in[2];
    const float* bl0   = (const float*)d_in[3];
    const float* Wr0   = (const float*)d_in[4];
    const float* Wl1   = (const float*)d_in[5];
    const float* bl1   = (const float*)d_in[6];
    const float* Wr1   = (const float*)d_in[7];
    const float* Wl2   = (const float*)d_in[8];
    const float* bl2   = (const float*)d_in[9];
    const float* Wr2   = (const float*)d_in[10];
    const float* gamma = (const float*)d_in[11];
    const float* beta  = (const float*)d_in[12];
    float* out = (float*)d_out;

    const int* srcp = ei;
    const int* dstp = ei + NE;

    static bool attr_set = false;
    if (!attr_set) {
        cudaFuncSetAttribute(mono_kernel,
                             cudaFuncAttributeMaxDynamicSharedMemorySize, SMEM_BYTES);
        attr_set = true;
    }

    mono_kernel<<<NB, NT, SMEM_BYTES>>>(x, srcp, dstp,
                                        Wl0, bl0, Wr0,
                                        Wl1, bl1, Wr1,
                                        Wl2, bl2, Wr2,
                                        gamma, beta, out);
}

// round 15
// speedup vs baseline: 1.1593x; 1.1593x over previous
#include <cuda_runtime.h>
#include <cuda_bf16.h>
#include <cuda_fp16.h>
#include <mma.h>
#include <cstdint>

using namespace nvcuda;

#define NN 50000
#define NE 800000
#define D 128
#define NB 148
#define NT 512
#define GS (NB * NT)
#define NWARPS (NT / 32)             // 16
#define CHUNK ((NN + NB - 1) / NB)   // 338
#define NT64 ((NN + 63) / 64)        // 782 64-row tiles
#define LDA 136                       // fp16 smem leading dim (272 B rows)
#define LDS_ 132                      // f32 staging leading dim
#define WSZ (128 * 136)               // one W plane (elements)

// smem byte offsets (within 1024-aligned base)
#define O_WLH 0
#define O_WLL 34816
#define O_WRH 69632
#define O_WRL 104448
#define O_AX  139264                  // a1 tile (17408 B)
#define O_AY  156672                  // mean tile (17408 B)
#define O_ST  174080                  // f32 staging (33792 B)
#define SMEM_BYTES (207872 + 1024)

typedef unsigned long long u64;

// -------- device scratch --------
__device__ unsigned g_gen = 0;
__device__ unsigned g_arrive = 0;
__device__ int   g_cnt[NN];
__device__ int   g_off[NN + 1];
__device__ int   g_pos[NN];
__device__ int   g_srcs[NE];
__device__ int   g_bsum[NB];
__device__ float g_ps[NB * D];
__device__ float g_ps2[NB * D];
// pre-split weights: fp16 hi + fp16 lo-correction (6 matrices, ld=136)
__device__ __half g_wh[6 * WSZ];
__device__ __half g_wl[6 * WSZ];
// single-plane fp16 feature buffers (ld = 128)
__device__ __half g_x16[NN * D];
__device__ __half g_m16[NN * D];
__device__ __half g_h016[NN * D];
__device__ __half g_h116[NN * D];

// -------- helpers --------
__device__ __forceinline__ uint2 half4(float4 v) {
    uint2 r;
    *(__half2*)&r.x = __floats2half2_rn(v.x, v.y);
    *(__half2*)&r.y = __floats2half2_rn(v.z, v.w);
    return r;
}
// fp16 hi/lo split of fp32 (W conversion)
__device__ __forceinline__ void split4h(float4 v, uint2& h, uint2& l) {
    __half hx = __float2half_rn(v.x);
    __half hy = __float2half_rn(v.y);
    __half hz = __float2half_rn(v.z);
    __half hw = __float2half_rn(v.w);
    *(__half2*)&h.x = __halves2half2(hx, hy);
    *(__half2*)&h.y = __halves2half2(hz, hw);
    *(__half2*)&l.x = __floats2half2_rn(v.x - __half2float(hx),
                                        v.y - __half2float(hy));
    *(__half2*)&l.y = __floats2half2_rn(v.z - __half2float(hz),
                                        v.w - __half2float(hw));
}
__device__ __forceinline__ void cpa16(uint32_t saddr, const void* gptr) {
    asm volatile("cp.async.cg.shared.global [%0], [%1], 16;"
                 :: "r"(saddr), "l"(gptr) : "memory");
}
#define CP_COMMIT() asm volatile("cp.async.commit_group;" ::: "memory")
#define CP_WAIT0()  asm volatile("cp.async.wait_group 0;" ::: "memory")

// -------- grid-wide software barrier --------
__device__ __forceinline__ void gbar() {
    __syncthreads();
    if (threadIdx.x == 0) {
        __threadfence();
        unsigned gen = atomicAdd(&g_gen, 0u);
        unsigned arrived = atomicAdd(&g_arrive, 1u) + 1u;
        if (arrived == NB) {
            atomicExch(&g_arrive, 0u);
            __threadfence();
            atomicAdd(&g_gen, 1u);
        } else {
            while (atomicAdd(&g_gen, 0u) == gen) { __nanosleep(128); }
        }
        __threadfence();
    }
    __syncthreads();
}

// -------- mean aggregation: fp16 gather, fp16 mean output --------
__device__ __forceinline__ void agg_phase(const __half* __restrict__ h16) {
    const int lane = threadIdx.x & 31;
    const int warp = threadIdx.x >> 5;
    const int gw0 = blockIdx.x * NWARPS + warp;
    for (int n = gw0; n < NN; n += NB * NWARPS) {
        int beg = g_off[n];
        int end = g_off[n + 1];
        float4 a0 = make_float4(0.f, 0.f, 0.f, 0.f);
        float4 a1 = make_float4(0.f, 0.f, 0.f, 0.f);
        int i = beg;
#define GATHER1(s, acc) do { \
            uint2 u = __ldg((const uint2*)(h16 + (size_t)(s) * D + lane * 4)); \
            float2 p = __half22float2(*(const __half2*)&u.x); \
            float2 q = __half22float2(*(const __half2*)&u.y); \
            (acc).x += p.x; (acc).y += p.y; (acc).z += q.x; (acc).w += q.y; } while (0)
        for (; i + 7 < end; i += 8) {
            int s0 = __ldg(&g_srcs[i]);
            int s1 = __ldg(&g_srcs[i + 1]);
            int s2 = __ldg(&g_srcs[i + 2]);
            int s3 = __ldg(&g_srcs[i + 3]);
            int s4 = __ldg(&g_srcs[i + 4]);
            int s5 = __ldg(&g_srcs[i + 5]);
            int s6 = __ldg(&g_srcs[i + 6]);
            int s7 = __ldg(&g_srcs[i + 7]);
            GATHER1(s0, a0); GATHER1(s1, a0); GATHER1(s2, a0); GATHER1(s3, a0);
            GATHER1(s4, a1); GATHER1(s5, a1); GATHER1(s6, a1); GATHER1(s7, a1);
        }
        for (; i < end; i++) { GATHER1(__ldg(&g_srcs[i]), a0); }
#undef GATHER1
        float inv = 1.0f / fmaxf((float)(end - beg), 1.0f);
        float4 r;
        r.x = (a0.x + a1.x) * inv;
        r.y = (a0.y + a1.y) * inv;
        r.z = (a0.z + a1.z) * inv;
        r.w = (a0.w + a1.w) * inv;
        *(uint2*)(g_m16 + (size_t)n * D + lane * 4) = half4(r);
    }
}

// -------- 64-row single-plane A-tile async copy: 1024 x 16B --------
__device__ __forceinline__ void copy64_async(const __half* __restrict__ A,
                                             int row0, uint32_t sdst) {
#pragma unroll
    for (int it = 0; it < 2; it++) {
        int idx = threadIdx.x + it * NT;   // 0..1023
        int r = idx >> 4, g = idx & 15;
        int row = min(row0 + r, NN - 1);
        cpa16(sdst + r * 272 + g * 16, A + (size_t)row * D + g * 8);
    }
}

// -------- MMA: A fp16 single plane, W fp16 hi+lo (2 products) --------
__device__ __forceinline__ void mma64(
    wmma::fragment<wmma::accumulator, 16, 16, 16, float> fc[2],
    const __half* a,
    const __half* wh, const __half* wl,
    int wr_, int wc_) {
#pragma unroll
    for (int ks = 0; ks < 8; ks++) {
        wmma::fragment<wmma::matrix_a, 16, 16, 16, __half,
                       wmma::row_major> fa;
        wmma::fragment<wmma::matrix_b, 16, 16, 16, __half,
                       wmma::col_major> fb_hi[2], fb_lo[2];
        wmma::load_matrix_sync(fa, a + (wr_ * 16) * LDA + ks * 16, LDA);
#pragma unroll
        for (int j = 0; j < 2; j++) {
            const int c = wc_ * 32 + j * 16;
            wmma::load_matrix_sync(fb_hi[j], wh + c * LDA + ks * 16, LDA);
            wmma::load_matrix_sync(fb_lo[j], wl + c * LDA + ks * 16, LDA);
        }
#pragma unroll
        for (int j = 0; j < 2; j++) {
            wmma::mma_sync(fc[j], fa, fb_hi[j], fc[j]);
            wmma::mma_sync(fc[j], fa, fb_lo[j], fc[j]);
        }
    }
}

// -------- cp.async pipelined fused dual GEMM: out = mean@Wl + a1@Wr + b ----
// MODE 0: relu -> o16. MODE 1: -> o16 + BN partials. MODE 2: fp32 outf.
template <int MODE>
__device__ __forceinline__ void gemm_cp(
    const __half* __restrict__ a1,
    int wml, int wmr,
    const float* __restrict__ bias,
    float* __restrict__ outf, __half* __restrict__ o16, char* base) {
    __half* wlh = (__half*)(base + O_WLH);
    __half* wll = (__half*)(base + O_WLL);
    __half* wrh = (__half*)(base + O_WRH);
    __half* wrl = (__half*)(base + O_WRL);
    __half* X = (__half*)(base + O_AX);
    __half* Y = (__half*)(base + O_AY);
    float* staging = (float*)(base + O_ST);

    const uint32_t sbase = (uint32_t)__cvta_generic_to_shared(base);
    const uint32_t sX = sbase + O_AX;
    const uint32_t sY = sbase + O_AY;

    const int tid = threadIdx.x;
    const int warp = tid >> 5;
    const int wr_ = warp >> 2;   // 0..3 -> rows wr_*16
    const int wc_ = warp & 3;    // 0..3 -> cols wc_*32

    // prologue: async W fill + first a1 tile
    {
        const char* s0 = (const char*)(g_wh + wml * WSZ);
        const char* s1 = (const char*)(g_wl + wml * WSZ);
        const char* s2 = (const char*)(g_wh + wmr * WSZ);
        const char* s3 = (const char*)(g_wl + wmr * WSZ);
        for (int i = tid; i < 2176; i += NT) {
            cpa16(sbase + O_WLH + i * 16, s0 + i * 16);
            cpa16(sbase + O_WLL + i * 16, s1 + i * 16);
            cpa16(sbase + O_WRH + i * 16, s2 + i * 16);
            cpa16(sbase + O_WRL + i * 16, s3 + i * 16);
        }
    }
    copy64_async(a1, blockIdx.x * 64, sX);
    CP_COMMIT();
    CP_WAIT0();
    __syncthreads();

    float bn_s[4] = {0.f, 0.f, 0.f, 0.f};
    float bn_s2[4] = {0.f, 0.f, 0.f, 0.f};

    for (int t = blockIdx.x; t < NT64; t += NB) {
        const int row0 = t * 64;
        wmma::fragment<wmma::accumulator, 16, 16, 16, float> fc[2];
#pragma unroll
        for (int j = 0; j < 2; j++) wmma::fill_fragment(fc[j], 0.f);

        // issue mean(t) copy into Y; overlap with a1 MMA on X
        copy64_async(g_m16, row0, sY);
        CP_COMMIT();
        mma64(fc, X, wrh, wrl, wr_, wc_);          // a1 @ Wr
        CP_WAIT0();
        __syncthreads();

        // issue a1(t+NB) into X; overlap with mean MMA + staging + epilogue
        int tn = t + NB;
        if (tn < NT64) copy64_async(a1, tn * 64, sX);
        CP_COMMIT();
        mma64(fc, Y, wlh, wll, wr_, wc_);          // mean @ Wl
        // staging region is disjoint from X/Y; warps write private areas
#pragma unroll
        for (int j = 0; j < 2; j++)
            wmma::store_matrix_sync(
                staging + (wr_ * 16) * LDS_ + wc_ * 32 + j * 16,
                fc[j], LDS_, wmma::mem_row_major);
        __syncthreads();

        // epilogue: 64 rows x 32 col-quads
        const int cq = tid & 31;
        float4 b4 = *(const float4*)(bias + cq * 4);
#pragma unroll
        for (int it = 0; it < 4; it++) {
            int idx = tid + it * NT;
            int r = idx >> 5;
            int row = row0 + r;
            if (row < NN) {
                float4 v = *(const float4*)(staging + r * LDS_ + cq * 4);
                v.x += b4.x; v.y += b4.y; v.z += b4.z; v.w += b4.w;
                size_t off = (size_t)row * D + cq * 4;
                if (MODE == 0) {
                    v.x = fmaxf(v.x, 0.f); v.y = fmaxf(v.y, 0.f);
                    v.z = fmaxf(v.z, 0.f); v.w = fmaxf(v.w, 0.f);
                    *(uint2*)(o16 + off) = half4(v);
                } else if (MODE == 1) {
                    bn_s[0] += v.x; bn_s[1] += v.y;
                    bn_s[2] += v.z; bn_s[3] += v.w;
                    bn_s2[0] += v.x * v.x; bn_s2[1] += v.y * v.y;
                    bn_s2[2] += v.z * v.z; bn_s2[3] += v.w * v.w;
                    *(uint2*)(o16 + off) = half4(v);
                } else {
                    *(float4*)(outf + off) = v;
                }
            }
        }
        CP_WAIT0();        // a1(t+NB) landed
        __syncthreads();   // X visible to all; staging reads done
    }

    if (MODE == 1) {
        float* bs = staging;
#pragma unroll
        for (int j = 0; j < 4; j++) {
            bs[j * NT + tid] = bn_s[j];
            bs[4 * NT + j * NT + tid] = bn_s2[j];
        }
        __syncthreads();
        if (tid < D) {
            int l = tid >> 2, j = tid & 3;
            float s = 0.f, s2 = 0.f;
#pragma unroll
            for (int w = 0; w < 16; w++) {
                s += bs[j * NT + l + w * 32];
                s2 += bs[4 * NT + j * NT + l + w * 32];
            }
            g_ps[blockIdx.x * D + tid] = s;
            g_ps2[blockIdx.x * D + tid] = s2;
        }
        __syncthreads();
    }
}

// -------- the mono-kernel --------
__global__ void __launch_bounds__(NT, 1)
mono_kernel(const float* __restrict__ x,
            const int* __restrict__ src, const int* __restrict__ dst,
            const float* __restrict__ Wl0, const float* __restrict__ bl0,
            const float* __restrict__ Wr0,
            const float* __restrict__ Wl1, const float* __restrict__ bl1,
            const float* __restrict__ Wr1,
            const float* __restrict__ Wl2, const float* __restrict__ bl2,
            const float* __restrict__ Wr2,
            const float* __restrict__ gamma, const float* __restrict__ beta,
            float* __restrict__ out) {
    extern __shared__ char smc[];
    char* base = (char*)(((uintptr_t)smc + 1023) & ~(uintptr_t)1023);
    const int tid = threadIdx.x;
    const int bid = blockIdx.x;
    const int gt = bid * NT + tid;
    const int lane = tid & 31;
    const int warp = tid >> 5;

    // ---- phase 1: histogram + x->fp16 + split all 6 W (fp16 hi/lo) ----
    for (int e = gt; e < NE; e += GS) atomicAdd(&g_cnt[dst[e]], 1);
    for (int i = gt; i < NN * 32; i += GS) {
        float4 v = __ldg((const float4*)(x + (size_t)i * 4));
        ((uint2*)g_x16)[i] = half4(v);
    }
    {
        const float* wm[6] = {Wl0, Wr0, Wl1, Wr1, Wl2, Wr2};
        for (int i = gt; i < 6 * 4096; i += GS) {
            int m = i >> 12;
            int rem = i & 4095;
            int r = rem >> 5, kq = rem & 31;
            float4 v = __ldg((const float4*)(wm[m] + r * D + kq * 4));
            uint2 h, l;
            split4h(v, h, l);
            *(uint2*)(g_wh + m * WSZ + r * LDA + kq * 4) = h;
            *(uint2*)(g_wl + m * WSZ + r * LDA + kq * 4) = l;
        }
    }
    gbar();

    // ---- phase 2: per-block chunk sums ----
    {
        __shared__ int red[NWARPS];
        int cb = bid * CHUNK;
        int v = 0;
        for (int i = tid; i < CHUNK; i += NT) {
            int idx = cb + i;
            if (idx < NN) v += g_cnt[idx];
        }
#pragma unroll
        for (int o = 16; o > 0; o >>= 1) v += __shfl_down_sync(0xffffffffu, v, o);
        if (lane == 0) red[warp] = v;
        __syncthreads();
        if (warp == 0) {
            int w = (lane < NWARPS) ? red[lane] : 0;
#pragma unroll
            for (int o = 8; o > 0; o >>= 1) w += __shfl_down_sync(0xffffffffu, w, o);
            if (lane == 0) g_bsum[bid] = w;
        }
    }
    gbar();

    // ---- phase 3: every block scans block sums locally ----
    __shared__ int s_boff;
    {
        __shared__ int sb[NB];
        if (tid < NB) sb[tid] = g_bsum[tid];
        __syncthreads();
        if (tid == 0) {
            int run = 0;
            for (int b = 0; b < NB; b++) { int v = sb[b]; sb[b] = run; run += v; }
            s_boff = sb[bid];
        }
        __syncthreads();
        if (bid == NB - 1 && tid == 0) g_off[NN] = NE;
    }

    // ---- phase 4: write offsets, reset g_cnt ----
    {
        __shared__ int wsum[NWARPS];
        int cb = bid * CHUNK;
        int idx = cb + tid;
        int v = (tid < CHUNK && idx < NN) ? g_cnt[idx] : 0;
        int inc = v;
#pragma unroll
        for (int o = 1; o < 32; o <<= 1) {
            int u = __shfl_up_sync(0xffffffffu, inc, o);
            if (lane >= o) inc += u;
        }
        if (lane == 31) wsum[warp] = inc;
        __syncthreads();
        if (warp == 0) {
            int w = (lane < NWARPS) ? wsum[lane] : 0;
            int wi = w;
#pragma unroll
            for (int o = 1; o < NWARPS; o <<= 1) {
                int u = __shfl_up_sync(0xffffffffu, wi, o);
                if (lane >= o) wi += u;
            }
            if (lane < NWARPS) wsum[lane] = wi - w;
        }
        __syncthreads();
        int excl = s_boff + wsum[warp] + inc - v;
        if (tid < CHUNK && idx < NN) {
            g_off[idx] = excl;
            g_pos[idx] = excl;
            g_cnt[idx] = 0;
        }
    }
    gbar();

    // ---- phase 5: scatter src by dst ----
    for (int e = gt; e < NE; e += GS) {
        int p = atomicAdd(&g_pos[dst[e]], 1);
        g_srcs[p] = src[e];
    }
    gbar();

    // ---- layer 0 ----
    agg_phase(g_x16);
    gbar();
    gemm_cp<0>(g_x16, 0, 1, bl0, nullptr, g_h016, base);
    gbar();

    // ---- layer 1 ----
    agg_phase(g_h016);
    gbar();
    gemm_cp<1>(g_h016, 2, 3, bl1, nullptr, g_h116, base);
    gbar();

    // ---- batchnorm finalize (replicated) + apply + relu (in place fp16) ----
    {
        __shared__ float s_scale[D], s_shift[D];
        __shared__ float r1[NT], r2[NT];
        int col = tid & 127;
        int part = tid >> 7;  // 0..3
        float s = 0.f, s2 = 0.f;
        for (int b = part; b < NB; b += 4) {
            s += g_ps[b * D + col];
            s2 += g_ps2[b * D + col];
        }
        r1[tid] = s; r2[tid] = s2;
        __syncthreads();
        if (part == 0) {
            double S = (double)r1[col] + (double)r1[col + 128] +
                       (double)r1[col + 256] + (double)r1[col + 384];
            double S2 = (double)r2[col] + (double)r2[col + 128] +
                        (double)r2[col + 256] + (double)r2[col + 384];
            double mu = S / (double)NN;
            double var = S2 / (double)NN - mu * mu;
            float inv = rsqrtf((float)var + 1e-5f);
            float sc = inv * gamma[col];
            s_scale[col] = sc;
            s_shift[col] = beta[col] - (float)mu * sc;
        }
        __syncthreads();
        for (int i = gt; i < NN * 32; i += GS) {
            uint2 u = ((const uint2*)g_h116)[i];
            float2 p = __half22float2(*(const __half2*)&u.x);
            float2 q = __half22float2(*(const __half2*)&u.y);
            float4 v = make_float4(p.x, p.y, q.x, q.y);
            int c = (i & 31) * 4;
            v.x = fmaxf(fmaf(v.x, s_scale[c + 0], s_shift[c + 0]), 0.f);
            v.y = fmaxf(fmaf(v.y, s_scale[c + 1], s_shift[c + 1]), 0.f);
            v.z = fmaxf(fmaf(v.z, s_scale[c + 2], s_shift[c + 2]), 0.f);
            v.w = fmaxf(fmaf(v.w, s_scale[c + 3], s_shift[c + 3]), 0.f);
            ((uint2*)g_h116)[i] = half4(v);
        }
    }
    gbar();

    // ---- layer 2 ----
    agg_phase(g_h116);
    gbar();
    gemm_cp<2>(g_h116, 4, 5, bl2, out, nullptr, base);
}

// -------- launch --------
extern "C" void kernel_launch(void* const* d_in, const int* in_sizes, int n_in,
                              void* d_out, int out_size) {
    const float* x     = (const float*)d_in[0];
    const int*   ei    = (const int*)d_in[1];
    const float* Wl0   = (const float*)d_in[2];
    const float* bl0   = (const float*)d_in[3];
    const float* Wr0   = (const float*)d_in[4];
    const float* Wl1   = (const float*)d_in[5];
    const float* bl1   = (const float*)d_in[6];
    const float* Wr1   = (const float*)d_in[7];
    const float* Wl2   = (const float*)d_in[8];
    const float* bl2   = (const float*)d_in[9];
    const float* Wr2   = (const float*)d_in[10];
    const float* gamma = (const float*)d_in[11];
    const float* beta  = (const float*)d_in[12];
    float* out = (float*)d_out;

    const int* srcp = ei;
    const int* dstp = ei + NE;

    static bool attr_set = false;
    if (!attr_set) {
        cudaFuncSetAttribute(mono_kernel,
                             cudaFuncAttributeMaxDynamicSharedMemorySize, SMEM_BYTES);
        attr_set = true;
    }

    mono_kernel<<<NB, NT, SMEM_BYTES>>>(x, srcp, dstp,
                                        Wl0, bl0, Wr0,
                                        Wl1, bl1, Wr1,
                                        Wl2, bl2, Wr2,
                                        gamma, beta, out);
}